// round 9
// baseline (speedup 1.0000x reference)
#include <cuda_runtime.h>
#include <cstdint>

typedef unsigned long long ull;

#define MAXF  20000
#define KK    50
#define CAP   768        // per-row candidate buffer
#define NBIN  512        // coarse bins = float bits >> 22
#define RB    128        // reduce stage-1 blocks

#define G     32         // grid cells per axis
#define NC    (G*G*G)    // 32768
#define BMIN  (-4.5f)
#define HH    (9.0f/32.0f)
#define INVH  (32.0f/9.0f)

// ---------------- scratch ----------------
__device__ float4 g_cent4[MAXF];       // centroid xyz, w = 0.5*|c|^2
__device__ float4 g_v0[MAXF], g_v1[MAXF], g_v2[MAXF];
__device__ float4 g_nun[MAXF];
__device__ float4 g_nrm[MAXF];
__device__ int    g_nbr[MAXF * KK];
__device__ float  g_contrib[MAXF];
__device__ double g_partial[RB];

__device__ int    g_cellcnt[NC];
__device__ int    g_cellfill[NC];
__device__ int    g_cellstart[NC + 1];
__device__ int    g_cellid[MAXF];
__device__ int    g_part[128];
__device__ int    g_partpre[129];
__device__ float4 g_scent[MAXF];       // cell-sorted centroids
__device__ int    g_sface[MAXF];       // original face index per sorted slot

// canonical squared distance bits: d = max(2*((ci_h + cj_h) - dot), 0)
__device__ __forceinline__ unsigned canon_bits(float4 c, float4 a) {
    float dot = c.x * a.x + c.y * a.y + c.z * a.z;
    float d = fmaxf(2.0f * ((c.w + a.w) - dot), 0.0f);
    return __float_as_uint(d);
}

__device__ __forceinline__ int bin1(float x) {
    int i = (int)floorf((x - BMIN) * INVH);
    return i < 0 ? 0 : (i > G - 1 ? G - 1 : i);
}

// ---------------- zero grid counters ----------------
__global__ void zero_kernel() {
    int i = blockIdx.x * blockDim.x + threadIdx.x;
    if (i < NC) { g_cellcnt[i] = 0; g_cellfill[i] = 0; }
}

// ---------------- kernel: per-face geometry + cell binning ----------------
__global__ void prep_kernel(const float* __restrict__ verts,
                            const int* __restrict__ faces, int F) {
    int f = blockIdx.x * blockDim.x + threadIdx.x;
    if (f >= F) return;
    int i0 = faces[3 * f + 0], i1 = faces[3 * f + 1], i2 = faces[3 * f + 2];
    float v0x = verts[3 * i0 + 0], v0y = verts[3 * i0 + 1], v0z = verts[3 * i0 + 2];
    float v1x = verts[3 * i1 + 0], v1y = verts[3 * i1 + 1], v1z = verts[3 * i1 + 2];
    float v2x = verts[3 * i2 + 0], v2y = verts[3 * i2 + 1], v2z = verts[3 * i2 + 2];

    float e1x = v1x - v0x, e1y = v1y - v0y, e1z = v1z - v0z;
    float e2x = v2x - v0x, e2y = v2y - v0y, e2z = v2z - v0z;
    float nx = e1y * e2z - e1z * e2y;
    float ny = e1z * e2x - e1x * e2z;
    float nz = e1x * e2y - e1y * e2x;
    float nn = sqrtf(nx * nx + ny * ny + nz * nz) + 1e-8f;

    float cx = (v0x + v1x + v2x) / 3.0f;
    float cy = (v0y + v1y + v2y) / 3.0f;
    float cz = (v0z + v1z + v2z) / 3.0f;
    float hsq = 0.5f * (cx * cx + cy * cy + cz * cz);

    g_cent4[f] = make_float4(cx, cy, cz, hsq);
    g_v0[f]    = make_float4(v0x, v0y, v0z, 0.f);
    g_v1[f]    = make_float4(v1x, v1y, v1z, 0.f);
    g_v2[f]    = make_float4(v2x, v2y, v2z, 0.f);
    g_nun[f]   = make_float4(nx, ny, nz, 0.f);
    g_nrm[f]   = make_float4(nx / nn, ny / nn, nz / nn, 0.f);

    int c = (bin1(cz) * G + bin1(cy)) * G + bin1(cx);
    g_cellid[f] = c;
    atomicAdd(&g_cellcnt[c], 1);
}

// ---------------- 3-kernel exclusive scan of g_cellcnt ----------------
__global__ void scanA_kernel() {              // 128 blocks x 256 threads
    __shared__ int s[256];
    int b = blockIdx.x, t = threadIdx.x;
    s[t] = g_cellcnt[b * 256 + t];
    __syncthreads();
    for (int o = 128; o; o >>= 1) {
        if (t < o) s[t] += s[t + o];
        __syncthreads();
    }
    if (t == 0) g_part[b] = s[0];
}

__global__ void scanB_kernel() {              // 1 block x 128 threads
    __shared__ int s[128];
    int t = threadIdx.x;
    int v = g_part[t];
    s[t] = v;
    __syncthreads();
    for (int o = 1; o < 128; o <<= 1) {
        int add = (t >= o) ? s[t - o] : 0;
        __syncthreads();
        s[t] += add;
        __syncthreads();
    }
    g_partpre[t] = s[t] - v;
    if (t == 127) g_partpre[128] = s[127];
}

__global__ void scanC_kernel() {              // 128 blocks x 256 threads
    __shared__ int s[256];
    int b = blockIdx.x, t = threadIdx.x;
    int v = g_cellcnt[b * 256 + t];
    s[t] = v;
    __syncthreads();
    for (int o = 1; o < 256; o <<= 1) {
        int add = (t >= o) ? s[t - o] : 0;
        __syncthreads();
        s[t] += add;
        __syncthreads();
    }
    g_cellstart[b * 256 + t] = g_partpre[b] + s[t] - v;
    if (b == 127 && t == 255) g_cellstart[NC] = g_partpre[128];
}

// ---------------- scatter into cell-sorted order ----------------
__global__ void scatter_kernel(int F) {
    int f = blockIdx.x * blockDim.x + threadIdx.x;
    if (f >= F) return;
    int c = g_cellid[f];
    int pos = g_cellstart[c] + atomicAdd(&g_cellfill[c], 1);
    g_scent[pos] = g_cent4[f];
    g_sface[pos] = f;
}

// ---------------- query: exact grid kNN, one warp per row ----------------
__global__ void __launch_bounds__(128) query_kernel(int F, int kp1) {
    __shared__ ull bufs[4 * CAP];
    __shared__ int hist[4 * NBIN];

    int tid = threadIdx.x;
    int lane = tid & 31;
    int w = tid >> 5;
    int ri = blockIdx.x * 4 + w;
    if (ri >= F) return;
    const unsigned FULL = 0xffffffffu;
    unsigned lmask = (1u << lane) - 1u;

    ull* bw = bufs + w * CAP;
    int* h = hist + w * NBIN;

    float4 q = g_cent4[ri];
    int cx = bin1(q.x), cy = bin1(q.y), cz = bin1(q.z);

    int cnt = 0;
    unsigned thr = 0x7F800000u;
    float thrpv = __int_as_float(0x7F800000);

    // warp-local compaction: tighten thr, filter buffer in place
    auto compact = [&]() {
        for (int b = lane; b < NBIN; b += 32) h[b] = 0;
        __syncwarp();
        for (int e = lane; e < cnt; e += 32)
            atomicAdd(&h[(unsigned)(bw[e] >> 54)], 1);
        __syncwarp();
        int b0l = lane * 16, s = 0;
        #pragma unroll
        for (int b = 0; b < 16; ++b) s += h[b0l + b];
        int cum = s;
        #pragma unroll
        for (int o = 1; o < 32; o <<= 1) {
            int t = __shfl_up_sync(FULL, cum, o);
            if (lane >= o) cum += t;
        }
        unsigned bal = __ballot_sync(FULL, cum >= kp1);
        int L = __ffs(bal) - 1;
        int cbef = __shfl_sync(FULL, cum - s, L);
        int Bc = 0, cB = 0;
        if (lane == L) {
            int c = cbef, b = L * 16;
            for (;; ++b) { if (c + h[b] >= kp1) break; c += h[b]; }
            Bc = b; cB = c;
        }
        Bc = __shfl_sync(FULL, Bc, L);
        cB = __shfl_sync(FULL, cB, L);
        __syncwarp();
        if (lane < 16) h[lane] = 0;
        __syncwarp();
        for (int e = lane; e < cnt; e += 32) {
            unsigned bits = (unsigned)(bw[e] >> 32);
            if ((bits >> 22) == (unsigned)Bc)
                atomicAdd(&h[(bits >> 18) & 15], 1);
        }
        __syncwarp();
        int S = 0;
        if (lane == 0) {
            int c = cB, ssb = 0;
            for (;; ++ssb) { if (c + h[ssb] >= kp1) break; c += h[ssb]; }
            S = ssb;
        }
        S = __shfl_sync(FULL, S, 0);
        unsigned fine = ((unsigned)Bc << 4) | (unsigned)S;
        unsigned thrb = (fine + 1u) << 18;
        if (thrb > 0x7F800000u) thrb = 0x7F800000u;
        unsigned thrp = (fine + 2u) << 18;
        if (thrp > 0x7F800000u) thrp = 0x7F800000u;
        int nb = 0;
        for (int i0 = 0; i0 < cnt; i0 += 32) {
            int e = i0 + lane;
            ull v = (e < cnt) ? bw[e] : ~0ull;
            bool keep = (e < cnt) && ((unsigned)(v >> 32) < thrb);
            unsigned m = __ballot_sync(FULL, keep);
            int pos = nb + __popc(m & lmask);
            __syncwarp();
            if (keep) bw[pos] = v;
            nb += __popc(m);
            __syncwarp();
        }
        cnt = nb;
        thr = thrb;
        thrpv = __uint_as_float(thrp);
    };

    // push all points of cell range [s0,s1) passing canonical filter
    auto pushcell = [&](int s0, int s1) {
        for (int base = s0; base < s1; base += 32) {
            int e = base + lane;
            bool act = e < s1;
            unsigned db = 0; unsigned jf = 0;
            if (act) {
                float4 a = g_scent[e];
                jf = (unsigned)g_sface[e];
                db = canon_bits(q, a);
                act = db < thr;
            }
            unsigned m = __ballot_sync(FULL, act);
            if (act) bw[cnt + __popc(m & lmask)] = ((ull)db << 32) | jf;
            cnt += __popc(m);
        }
    };

    // ---- phase A: expand rings until >= kp1 candidates, then set threshold
    int R = 0;
    for (;;) {
        for (int dz = -R; dz <= R; ++dz) {
            int az = cz + dz;
            if (az < 0 || az >= G) continue;
            for (int dy = -R; dy <= R; ++dy) {
                int ay = cy + dy;
                if (ay < 0 || ay >= G) continue;
                bool edge = (dz == -R || dz == R || dy == -R || dy == R);
                int step = (edge || R == 0) ? 1 : 2 * R;
                for (int dx = -R; dx <= R; dx += step) {
                    int ax = cx + dx;
                    if (ax < 0 || ax >= G) continue;
                    int c = (az * G + ay) * G + ax;
                    int s0 = g_cellstart[c], s1 = g_cellstart[c + 1];
                    if (s0 == s1) continue;
                    if (cnt + (s1 - s0) > CAP) compact();
                    pushcell(s0, s1);
                }
            }
        }
        if (cnt >= kp1) { compact(); break; }
        if (R >= G) break;
        ++R;
    }

    // ---- phase B: visit all further cells with mindist^2 < threshold ----
    for (int Rb = R + 1; Rb <= G; ++Rb) {
        float rb = (float)(Rb - 1) * HH;
        if (rb * rb >= thrpv) break;
        for (int dz = -Rb; dz <= Rb; ++dz) {
            int az = cz + dz;
            if (az < 0 || az >= G) continue;
            float loz = BMIN + az * HH, hiz = loz + HH;
            float dzm = fmaxf(fmaxf((az == 0) ? 0.f : loz - q.z,
                                    (az == G - 1) ? 0.f : q.z - hiz), 0.f);
            float dz2 = dzm * dzm;
            if (dz2 >= thrpv) continue;
            for (int dy = -Rb; dy <= Rb; ++dy) {
                int ay = cy + dy;
                if (ay < 0 || ay >= G) continue;
                float loy = BMIN + ay * HH, hiy = loy + HH;
                float dym = fmaxf(fmaxf((ay == 0) ? 0.f : loy - q.y,
                                        (ay == G - 1) ? 0.f : q.y - hiy), 0.f);
                float dzy = dz2 + dym * dym;
                if (dzy >= thrpv) continue;
                bool edge = (dz == -Rb || dz == Rb || dy == -Rb || dy == Rb);
                int step = edge ? 1 : 2 * Rb;
                for (int dx = -Rb; dx <= Rb; dx += step) {
                    int ax = cx + dx;
                    if (ax < 0 || ax >= G) continue;
                    float lox = BMIN + ax * HH, hix = lox + HH;
                    float dxm = fmaxf(fmaxf((ax == 0) ? 0.f : lox - q.x,
                                            (ax == G - 1) ? 0.f : q.x - hix), 0.f);
                    float m2 = dzy + dxm * dxm;
                    if (m2 >= thrpv) continue;
                    int c = (az * G + ay) * G + ax;
                    int s0 = g_cellstart[c], s1 = g_cellstart[c + 1];
                    if (s0 == s1) continue;
                    if (cnt + (s1 - s0) > CAP) compact();
                    pushcell(s0, s1);
                }
            }
        }
    }

    if (cnt > 96) compact();

    // ---- final exact selection by rank counting ----
    for (int e = lane; e < cnt; e += 32) {
        ull ke = bw[e];
        int rank = 0;
        for (int qq = 0; qq < cnt; ++qq) rank += (bw[qq] < ke);
        // rank 0 = global min (self / lowest-index tie) -> dropped
        if (rank >= 1 && rank < kp1)
            g_nbr[(size_t)ri * KK + rank - 1] = (int)(ke & 0xffffffffu);
    }
}

// ---------------- collision tests, 4 faces per block --------------
__global__ void __launch_bounds__(256) collide_kernel(const int* __restrict__ faces,
                               const float* __restrict__ prob, int F, int kk) {
    int f = blockIdx.x * 4 + (threadIdx.x >> 6);
    int t = threadIdx.x & 63;
    bool col = false;
    if (f < F && t < kk) {
        int i = f;
        int j = g_nbr[(size_t)i * KK + t];
        float4 v0i = g_v0[i], v1i = g_v1[i], v2i = g_v2[i];
        float4 ni  = g_nun[i], mi = g_nrm[i], ci = g_cent4[i];
        float4 v0j = g_v0[j], v1j = g_v1[j], v2j = g_v2[j];
        float4 nj  = g_nun[j], mj = g_nrm[j], cj = g_cent4[j];

        float ndot = fabsf(mi.x * mj.x + mi.y * mj.y + mi.z * mj.z);
        bool coplanar = ndot > 0.99f;

        bool inter;
        if (coplanar) {
            float dx = ci.x - cj.x, dy = ci.y - cj.y, dz = ci.z - cj.z;
            inter = sqrtf(dx * dx + dy * dy + dz * dz) < 1e-10f;
        } else {
            float dA0 = (v0j.x - v0i.x) * ni.x + (v0j.y - v0i.y) * ni.y + (v0j.z - v0i.z) * ni.z;
            float dA1 = (v1j.x - v0i.x) * ni.x + (v1j.y - v0i.y) * ni.y + (v1j.z - v0i.z) * ni.z;
            float dA2 = (v2j.x - v0i.x) * ni.x + (v2j.y - v0i.y) * ni.y + (v2j.z - v0i.z) * ni.z;
            bool condA = (dA0 * dA1 <= 0.f) || (dA0 * dA2 <= 0.f) || (dA1 * dA2 <= 0.f);
            float dB0 = (v0i.x - v0j.x) * nj.x + (v0i.y - v0j.y) * nj.y + (v0i.z - v0j.z) * nj.z;
            float dB1 = (v1i.x - v0j.x) * nj.x + (v1i.y - v0j.y) * nj.y + (v1i.z - v0j.z) * nj.z;
            float dB2 = (v2i.x - v0j.x) * nj.x + (v2i.y - v0j.y) * nj.y + (v2i.z - v0j.z) * nj.z;
            bool condB = (dB0 * dB1 <= 0.f) || (dB0 * dB2 <= 0.f) || (dB1 * dB2 <= 0.f);
            inter = condA && condB;
        }

        int a0 = faces[3 * i + 0], a1 = faces[3 * i + 1], a2 = faces[3 * i + 2];
        int b0 = faces[3 * j + 0], b1 = faces[3 * j + 1], b2 = faces[3 * j + 2];
        bool f1 = (a1 != a0);
        bool f2 = (a2 != a0) && (a2 != a1);
        int shared = 0;
        if (a0 == b0 || a0 == b1 || a0 == b2) shared++;
        if (f1 && (a1 == b0 || a1 == b1 || a1 == b2)) shared++;
        if (f2 && (a2 == b0 || a2 == b1 || a2 == b2)) shared++;
        bool adjacent = shared >= 2;

        col = inter && !adjacent;
    }

    unsigned bal = __ballot_sync(0xffffffffu, col);
    __shared__ int wc[8];
    if ((threadIdx.x & 31) == 0) wc[threadIdx.x >> 5] = __popc(bal);
    __syncthreads();
    if (threadIdx.x < 4) {
        int f2 = blockIdx.x * 4 + threadIdx.x;
        if (f2 < F)
            g_contrib[f2] = prob[f2] * (float)(wc[2 * threadIdx.x] + wc[2 * threadIdx.x + 1]);
    }
}

// ---------------- deterministic two-stage reduction ------------
__global__ void reduce1_kernel(int F) {
    __shared__ double ps[256];
    int tid = threadIdx.x;
    double s = 0.0;
    for (int i = blockIdx.x * 256 + tid; i < F; i += RB * 256)
        s += (double)g_contrib[i];
    ps[tid] = s;
    __syncthreads();
    for (int o = 128; o; o >>= 1) {
        if (tid < o) ps[tid] += ps[tid + o];
        __syncthreads();
    }
    if (tid == 0) g_partial[blockIdx.x] = ps[0];
}

__global__ void reduce2_kernel(float* __restrict__ out) {
    __shared__ double ps[RB];
    int tid = threadIdx.x;
    ps[tid] = g_partial[tid];
    __syncthreads();
    for (int o = RB / 2; o; o >>= 1) {
        if (tid < o) ps[tid] += ps[tid + o];
        __syncthreads();
    }
    if (tid == 0) out[0] = (float)ps[0];
}

// ---------------- launch ----------------
extern "C" void kernel_launch(void* const* d_in, const int* in_sizes, int n_in,
                              void* d_out, int out_size) {
    const float* verts = (const float*)d_in[0];
    const int*   faces = (const int*)d_in[1];
    const float* prob  = (const float*)d_in[2];
    float* out = (float*)d_out;

    int F = in_sizes[1] / 3;
    if (F > MAXF) F = MAXF;
    int kk = (F - 1 < KK) ? (F - 1) : KK;
    int kp1 = kk + 1;

    zero_kernel<<<(NC + 255) / 256, 256>>>();
    prep_kernel<<<(F + 255) / 256, 256>>>(verts, faces, F);
    scanA_kernel<<<128, 256>>>();
    scanB_kernel<<<1, 128>>>();
    scanC_kernel<<<128, 256>>>();
    scatter_kernel<<<(F + 255) / 256, 256>>>(F);

    query_kernel<<<(F + 3) / 4, 128>>>(F, kp1);

    collide_kernel<<<(F + 3) / 4, 256>>>(faces, prob, F, kk);

    reduce1_kernel<<<RB, 256>>>(F);
    reduce2_kernel<<<1, RB>>>(out);
}

// round 10
// speedup vs baseline: 1.4761x; 1.4761x over previous
#include <cuda_runtime.h>
#include <cstdint>

typedef unsigned long long ull;

#define MAXF  20000
#define KK    50
#define CAP   1024       // per-row candidate buffer
#define NBIN  512        // coarse bins = float bits >> 22
#define RB    128        // reduce stage-1 blocks

#define G     32         // grid cells per axis
#define NC    (G*G*G)    // 32768
#define BMIN  (-4.5f)
#define HH    (9.0f/32.0f)
#define INVH  (32.0f/9.0f)

// ---------------- scratch ----------------
__device__ float4 g_cent4[MAXF];       // centroid xyz, w = 0.5*|c|^2
__device__ float4 g_v0[MAXF], g_v1[MAXF], g_v2[MAXF];
__device__ float4 g_nun[MAXF];
__device__ float4 g_nrm[MAXF];
__device__ int    g_nbr[MAXF * KK];
__device__ float  g_contrib[MAXF];
__device__ double g_partial[RB];

__device__ int    g_cellcnt[NC];       // zero at load; re-zeroed by cleanup
__device__ int    g_cellfill[NC];
__device__ int    g_cellstart[NC + 1];
__device__ int    g_cellid[MAXF];
__device__ float4 g_scent[MAXF];       // cell-sorted centroids
__device__ int    g_sface[MAXF];       // original face index per sorted slot

// canonical squared distance bits: d = max(2*((ci_h + cj_h) - dot), 0)
__device__ __forceinline__ unsigned canon_bits(float4 c, float4 a) {
    float dot = c.x * a.x + c.y * a.y + c.z * a.z;
    float d = fmaxf(2.0f * ((c.w + a.w) - dot), 0.0f);
    return __float_as_uint(d);
}

__device__ __forceinline__ int bin1(float x) {
    int i = (int)floorf((x - BMIN) * INVH);
    return i < 0 ? 0 : (i > G - 1 ? G - 1 : i);
}

// ---------------- kernel 1: per-face geometry + cell binning ----------------
__global__ void prep_kernel(const float* __restrict__ verts,
                            const int* __restrict__ faces, int F) {
    int f = blockIdx.x * blockDim.x + threadIdx.x;
    if (f >= F) return;
    int i0 = faces[3 * f + 0], i1 = faces[3 * f + 1], i2 = faces[3 * f + 2];
    float v0x = verts[3 * i0 + 0], v0y = verts[3 * i0 + 1], v0z = verts[3 * i0 + 2];
    float v1x = verts[3 * i1 + 0], v1y = verts[3 * i1 + 1], v1z = verts[3 * i1 + 2];
    float v2x = verts[3 * i2 + 0], v2y = verts[3 * i2 + 1], v2z = verts[3 * i2 + 2];

    float e1x = v1x - v0x, e1y = v1y - v0y, e1z = v1z - v0z;
    float e2x = v2x - v0x, e2y = v2y - v0y, e2z = v2z - v0z;
    float nx = e1y * e2z - e1z * e2y;
    float ny = e1z * e2x - e1x * e2z;
    float nz = e1x * e2y - e1y * e2x;
    float nn = sqrtf(nx * nx + ny * ny + nz * nz) + 1e-8f;

    float cx = (v0x + v1x + v2x) / 3.0f;
    float cy = (v0y + v1y + v2y) / 3.0f;
    float cz = (v0z + v1z + v2z) / 3.0f;
    float hsq = 0.5f * (cx * cx + cy * cy + cz * cz);

    g_cent4[f] = make_float4(cx, cy, cz, hsq);
    g_v0[f]    = make_float4(v0x, v0y, v0z, 0.f);
    g_v1[f]    = make_float4(v1x, v1y, v1z, 0.f);
    g_v2[f]    = make_float4(v2x, v2y, v2z, 0.f);
    g_nun[f]   = make_float4(nx, ny, nz, 0.f);
    g_nrm[f]   = make_float4(nx / nn, ny / nn, nz / nn, 0.f);

    int c = (bin1(cz) * G + bin1(cy)) * G + bin1(cx);
    g_cellid[f] = c;
    atomicAdd(&g_cellcnt[c], 1);
}

// ---------------- single-block exclusive scan of g_cellcnt (NC=32768) ------
__global__ void scan_kernel() {
    __shared__ int s[1024];
    int t = threadIdx.x;
    int base = t * 32;
    int loc[32];
    int sum = 0;
    #pragma unroll
    for (int i = 0; i < 32; ++i) { loc[i] = g_cellcnt[base + i]; sum += loc[i]; }
    s[t] = sum;
    __syncthreads();
    for (int o = 1; o < 1024; o <<= 1) {
        int add = (t >= o) ? s[t - o] : 0;
        __syncthreads();
        s[t] += add;
        __syncthreads();
    }
    int pre = s[t] - sum;
    #pragma unroll
    for (int i = 0; i < 32; ++i) { g_cellstart[base + i] = pre; pre += loc[i]; }
    if (t == 1023) g_cellstart[NC] = pre;
}

// ---------------- scatter into cell-sorted order ----------------
__global__ void scatter_kernel(int F) {
    int f = blockIdx.x * blockDim.x + threadIdx.x;
    if (f >= F) return;
    int c = g_cellid[f];
    int pos = g_cellstart[c] + atomicAdd(&g_cellfill[c], 1);
    g_scent[pos] = g_cent4[f];
    g_sface[pos] = f;
}

// ---------------- query: exact grid kNN, one warp per row, span-based ------
__global__ void __launch_bounds__(128) query_kernel(int F, int kp1) {
    __shared__ ull bufs[4 * CAP];
    __shared__ int hist[4 * NBIN];

    int tid = threadIdx.x;
    int lane = tid & 31;
    int w = tid >> 5;
    int ri = blockIdx.x * 4 + w;
    if (ri >= F) return;
    const unsigned FULL = 0xffffffffu;
    unsigned lmask = (1u << lane) - 1u;

    ull* bw = bufs + w * CAP;
    int* h = hist + w * NBIN;

    float4 qv = g_cent4[ri];
    int cx = bin1(qv.x), cy = bin1(qv.y), cz = bin1(qv.z);

    int cnt = 0;
    unsigned thr = 0x7F800000u;
    float thrpv = __int_as_float(0x7F800000);

    // warp-local compaction: tighten thr, filter buffer in place
    auto compact = [&]() {
        for (int b = lane; b < NBIN; b += 32) h[b] = 0;
        __syncwarp();
        for (int e = lane; e < cnt; e += 32)
            atomicAdd(&h[(unsigned)(bw[e] >> 54)], 1);
        __syncwarp();
        int b0l = lane * 16, s = 0;
        #pragma unroll
        for (int b = 0; b < 16; ++b) s += h[b0l + b];
        int cum = s;
        #pragma unroll
        for (int o = 1; o < 32; o <<= 1) {
            int t = __shfl_up_sync(FULL, cum, o);
            if (lane >= o) cum += t;
        }
        unsigned bal = __ballot_sync(FULL, cum >= kp1);
        int L = __ffs(bal) - 1;
        int cbef = __shfl_sync(FULL, cum - s, L);
        int Bc = 0, cB = 0;
        if (lane == L) {
            int c = cbef, b = L * 16;
            for (;; ++b) { if (c + h[b] >= kp1) break; c += h[b]; }
            Bc = b; cB = c;
        }
        Bc = __shfl_sync(FULL, Bc, L);
        cB = __shfl_sync(FULL, cB, L);
        __syncwarp();
        if (lane < 16) h[lane] = 0;
        __syncwarp();
        for (int e = lane; e < cnt; e += 32) {
            unsigned bits = (unsigned)(bw[e] >> 32);
            if ((bits >> 22) == (unsigned)Bc)
                atomicAdd(&h[(bits >> 18) & 15], 1);
        }
        __syncwarp();
        int S = 0;
        if (lane == 0) {
            int c = cB, ssb = 0;
            for (;; ++ssb) { if (c + h[ssb] >= kp1) break; c += h[ssb]; }
            S = ssb;
        }
        S = __shfl_sync(FULL, S, 0);
        unsigned fine = ((unsigned)Bc << 4) | (unsigned)S;
        unsigned thrb = (fine + 1u) << 18;
        if (thrb > 0x7F800000u) thrb = 0x7F800000u;
        unsigned thrp = (fine + 2u) << 18;
        if (thrp > 0x7F800000u) thrp = 0x7F800000u;
        int nb = 0;
        for (int i0 = 0; i0 < cnt; i0 += 32) {
            int e = i0 + lane;
            ull v = (e < cnt) ? bw[e] : ~0ull;
            bool keep = (e < cnt) && ((unsigned)(v >> 32) < thrb);
            unsigned m = __ballot_sync(FULL, keep);
            int pos = nb + __popc(m & lmask);
            __syncwarp();
            if (keep) bw[pos] = v;
            nb += __popc(m);
            __syncwarp();
        }
        cnt = nb;
        thr = thrb;
        thrpv = __uint_as_float(thrp);
    };

    // dense push of a contiguous sorted-point span [s0,s1)
    auto pushspan = [&](int s0, int s1) {
        for (int base = s0; base < s1; base += 32) {
            if (cnt + 32 > CAP && cnt >= kp1) compact();
            int e = base + lane;
            bool act = e < s1;
            unsigned db = 0; unsigned jf = 0;
            if (act) {
                float4 a = g_scent[e];
                jf = (unsigned)g_sface[e];
                db = canon_bits(qv, a);
                act = db < thr;
            }
            unsigned m = __ballot_sync(FULL, act);
            if (act) bw[cnt + __popc(m & lmask)] = ((ull)db << 32) | jf;
            cnt += __popc(m);
            if (cnt > CAP) cnt = CAP;
        }
    };

    // ---- find minimal box R with count >= kp1 (prefix-sum count only) ----
    int R = 0;
    int z0, z1, y0, y1, x0, x1;
    for (;;) {
        z0 = cz - R; if (z0 < 0) z0 = 0;
        z1 = cz + R; if (z1 > G - 1) z1 = G - 1;
        y0 = cy - R; if (y0 < 0) y0 = 0;
        y1 = cy + R; if (y1 > G - 1) y1 = G - 1;
        x0 = cx - R; if (x0 < 0) x0 = 0;
        x1 = cx + R; if (x1 > G - 1) x1 = G - 1;
        int ny = y1 - y0 + 1;
        int nrows = (z1 - z0 + 1) * ny;
        int total = 0;
        for (int b = lane; b < nrows; b += 32) {
            int az = z0 + b / ny, ay = y0 + b % ny;
            int rowb = (az * G + ay) * G;
            total += g_cellstart[rowb + x1 + 1] - g_cellstart[rowb + x0];
        }
        #pragma unroll
        for (int o = 16; o; o >>= 1) total += __shfl_xor_sync(FULL, total, o);
        if (total >= kp1 || R >= G) break;
        ++R;
    }

    // ---- phase A: push every row-span of box R (lane-parallel lookups) ----
    {
        int ny = y1 - y0 + 1;
        int nrows = (z1 - z0 + 1) * ny;
        for (int b0 = 0; b0 < nrows; b0 += 32) {
            int b = b0 + lane;
            int s0 = 0, s1 = 0;
            if (b < nrows) {
                int az = z0 + b / ny, ay = y0 + b % ny;
                int rowb = (az * G + ay) * G;
                s0 = g_cellstart[rowb + x0];
                s1 = g_cellstart[rowb + x1 + 1];
            }
            unsigned act = __ballot_sync(FULL, s1 > s0);
            while (act) {
                int L = __ffs(act) - 1; act &= act - 1;
                int t0 = __shfl_sync(FULL, s0, L);
                int t1 = __shfl_sync(FULL, s1, L);
                pushspan(t0, t1);
            }
        }
        compact();
    }

    // ---- phase B: all cells with box-mindist^2 < thr outside box R ----
    {
        float rt = sqrtf(thrpv) * 1.0001f + 1e-7f;
        int bz0 = bin1(qv.z - rt), bz1 = bin1(qv.z + rt);
        int by0 = bin1(qv.y - rt), by1 = bin1(qv.y + rt);
        int my = by1 - by0 + 1;
        int nr = (bz1 - bz0 + 1) * my;
        for (int b0 = 0; b0 < nr; b0 += 32) {
            int b = b0 + lane;
            int s0a = 0, s1a = 0, s0b = 0, s1b = 0;
            if (b < nr) {
                int az = bz0 + b / my, ay = by0 + b % my;
                float loz = BMIN + az * HH, hiz = loz + HH;
                float dzm = fmaxf(fmaxf((az == 0) ? 0.f : loz - qv.z,
                                        (az == G - 1) ? 0.f : qv.z - hiz), 0.f);
                float dz2 = dzm * dzm;
                if (dz2 < thrpv) {
                    float loy = BMIN + ay * HH, hiy = loy + HH;
                    float dym = fmaxf(fmaxf((ay == 0) ? 0.f : loy - qv.y,
                                            (ay == G - 1) ? 0.f : qv.y - hiy), 0.f);
                    float dzy = dz2 + dym * dym;
                    if (dzy < thrpv) {
                        float dxa = sqrtf(thrpv - dzy) * 1.0001f + 1e-7f;
                        int axlo = bin1(qv.x - dxa), axhi = bin1(qv.x + dxa);
                        int rowb = (az * G + ay) * G;
                        bool inbox = (az >= z0 && az <= z1 && ay >= y0 && ay <= y1);
                        if (inbox) {
                            if (axlo <= x0 - 1) {
                                s0a = g_cellstart[rowb + axlo];
                                s1a = g_cellstart[rowb + x0];
                            }
                            if (axhi >= x1 + 1) {
                                s0b = g_cellstart[rowb + x1 + 1];
                                s1b = g_cellstart[rowb + axhi + 1];
                            }
                        } else {
                            s0a = g_cellstart[rowb + axlo];
                            s1a = g_cellstart[rowb + axhi + 1];
                        }
                    }
                }
            }
            unsigned act = __ballot_sync(FULL, (s1a > s0a) | (s1b > s0b));
            while (act) {
                int L = __ffs(act) - 1; act &= act - 1;
                int t0 = __shfl_sync(FULL, s0a, L);
                int t1 = __shfl_sync(FULL, s1a, L);
                int u0 = __shfl_sync(FULL, s0b, L);
                int u1 = __shfl_sync(FULL, s1b, L);
                if (t1 > t0) pushspan(t0, t1);
                if (u1 > u0) pushspan(u0, u1);
            }
        }
    }

    compact();

    // ---- final exact selection by rank counting ----
    for (int e = lane; e < cnt; e += 32) {
        ull ke = bw[e];
        int rank = 0;
        for (int qq = 0; qq < cnt; ++qq) rank += (bw[qq] < ke);
        // rank 0 = global min (self / lowest-index tie) -> dropped
        if (rank >= 1 && rank < kp1)
            g_nbr[(size_t)ri * KK + rank - 1] = (int)(ke & 0xffffffffu);
    }
}

// ---------------- collision tests, 4 faces per block --------------
__global__ void __launch_bounds__(256) collide_kernel(const int* __restrict__ faces,
                               const float* __restrict__ prob, int F, int kk) {
    int f = blockIdx.x * 4 + (threadIdx.x >> 6);
    int t = threadIdx.x & 63;
    bool col = false;
    if (f < F && t < kk) {
        int i = f;
        int j = g_nbr[(size_t)i * KK + t];
        float4 v0i = g_v0[i], v1i = g_v1[i], v2i = g_v2[i];
        float4 ni  = g_nun[i], mi = g_nrm[i], ci = g_cent4[i];
        float4 v0j = g_v0[j], v1j = g_v1[j], v2j = g_v2[j];
        float4 nj  = g_nun[j], mj = g_nrm[j], cj = g_cent4[j];

        float ndot = fabsf(mi.x * mj.x + mi.y * mj.y + mi.z * mj.z);
        bool coplanar = ndot > 0.99f;

        bool inter;
        if (coplanar) {
            float dx = ci.x - cj.x, dy = ci.y - cj.y, dz = ci.z - cj.z;
            inter = sqrtf(dx * dx + dy * dy + dz * dz) < 1e-10f;
        } else {
            float dA0 = (v0j.x - v0i.x) * ni.x + (v0j.y - v0i.y) * ni.y + (v0j.z - v0i.z) * ni.z;
            float dA1 = (v1j.x - v0i.x) * ni.x + (v1j.y - v0i.y) * ni.y + (v1j.z - v0i.z) * ni.z;
            float dA2 = (v2j.x - v0i.x) * ni.x + (v2j.y - v0i.y) * ni.y + (v2j.z - v0i.z) * ni.z;
            bool condA = (dA0 * dA1 <= 0.f) || (dA0 * dA2 <= 0.f) || (dA1 * dA2 <= 0.f);
            float dB0 = (v0i.x - v0j.x) * nj.x + (v0i.y - v0j.y) * nj.y + (v0i.z - v0j.z) * nj.z;
            float dB1 = (v1i.x - v0j.x) * nj.x + (v1i.y - v0j.y) * nj.y + (v1i.z - v0j.z) * nj.z;
            float dB2 = (v2i.x - v0j.x) * nj.x + (v2i.y - v0j.y) * nj.y + (v2i.z - v0j.z) * nj.z;
            bool condB = (dB0 * dB1 <= 0.f) || (dB0 * dB2 <= 0.f) || (dB1 * dB2 <= 0.f);
            inter = condA && condB;
        }

        int a0 = faces[3 * i + 0], a1 = faces[3 * i + 1], a2 = faces[3 * i + 2];
        int b0 = faces[3 * j + 0], b1 = faces[3 * j + 1], b2 = faces[3 * j + 2];
        bool f1 = (a1 != a0);
        bool f2 = (a2 != a0) && (a2 != a1);
        int shared = 0;
        if (a0 == b0 || a0 == b1 || a0 == b2) shared++;
        if (f1 && (a1 == b0 || a1 == b1 || a1 == b2)) shared++;
        if (f2 && (a2 == b0 || a2 == b1 || a2 == b2)) shared++;
        bool adjacent = shared >= 2;

        col = inter && !adjacent;
    }

    unsigned bal = __ballot_sync(0xffffffffu, col);
    __shared__ int wc[8];
    if ((threadIdx.x & 31) == 0) wc[threadIdx.x >> 5] = __popc(bal);
    __syncthreads();
    if (threadIdx.x < 4) {
        int f2 = blockIdx.x * 4 + threadIdx.x;
        if (f2 < F)
            g_contrib[f2] = prob[f2] * (float)(wc[2 * threadIdx.x] + wc[2 * threadIdx.x + 1]);
    }
}

// ---------------- deterministic two-stage reduction ------------
__global__ void reduce1_kernel(int F) {
    __shared__ double ps[256];
    int tid = threadIdx.x;
    double s = 0.0;
    for (int i = blockIdx.x * 256 + tid; i < F; i += RB * 256)
        s += (double)g_contrib[i];
    ps[tid] = s;
    __syncthreads();
    for (int o = 128; o; o >>= 1) {
        if (tid < o) ps[tid] += ps[tid + o];
        __syncthreads();
    }
    if (tid == 0) g_partial[blockIdx.x] = ps[0];
}

__global__ void reduce2_kernel(float* __restrict__ out) {
    __shared__ double ps[RB];
    int tid = threadIdx.x;
    ps[tid] = g_partial[tid];
    __syncthreads();
    for (int o = RB / 2; o; o >>= 1) {
        if (tid < o) ps[tid] += ps[tid + o];
        __syncthreads();
    }
    if (tid == 0) out[0] = (float)ps[0];
}

// ---------------- cleanup: restore zeroed counters for next replay --------
__global__ void cleanup_kernel() {
    int i = blockIdx.x * blockDim.x + threadIdx.x;
    if (i < NC) { g_cellcnt[i] = 0; g_cellfill[i] = 0; }
}

// ---------------- launch ----------------
extern "C" void kernel_launch(void* const* d_in, const int* in_sizes, int n_in,
                              void* d_out, int out_size) {
    const float* verts = (const float*)d_in[0];
    const int*   faces = (const int*)d_in[1];
    const float* prob  = (const float*)d_in[2];
    float* out = (float*)d_out;

    int F = in_sizes[1] / 3;
    if (F > MAXF) F = MAXF;
    int kk = (F - 1 < KK) ? (F - 1) : KK;
    int kp1 = kk + 1;

    prep_kernel<<<(F + 255) / 256, 256>>>(verts, faces, F);
    scan_kernel<<<1, 1024>>>();
    scatter_kernel<<<(F + 255) / 256, 256>>>(F);

    query_kernel<<<(F + 3) / 4, 128>>>(F, kp1);   // 4th launch -> ncu profiles this

    collide_kernel<<<(F + 3) / 4, 256>>>(faces, prob, F, kk);

    reduce1_kernel<<<RB, 256>>>(F);
    reduce2_kernel<<<1, RB>>>(out);

    cleanup_kernel<<<(NC + 255) / 256, 256>>>();
}

// round 11
// speedup vs baseline: 1.7987x; 1.2185x over previous
#include <cuda_runtime.h>
#include <cstdint>

typedef unsigned long long ull;

#define MAXF  20000
#define KK    50
#define CAP   512        // per-row candidate buffer
#define NBIN  512        // coarse bins = float bits >> 22
#define RB    128        // reduce stage-1 blocks

#define G     32         // grid cells per axis
#define NC    (G*G*G)    // 32768
#define BMIN  (-4.5f)
#define HH    (9.0f/32.0f)
#define INVH  (32.0f/9.0f)

// ---------------- scratch ----------------
__device__ float4 g_cent4[MAXF];       // centroid xyz, w = 0.5*|c|^2
__device__ float4 g_v0[MAXF], g_v1[MAXF], g_v2[MAXF];
__device__ float4 g_nun[MAXF];
__device__ float4 g_nrm[MAXF];
__device__ float  g_contrib[MAXF];
__device__ double g_partial[RB];

__device__ int    g_cellcnt[NC];       // zero at load; re-zeroed by cleanup
__device__ int    g_cellfill[NC];
__device__ int    g_cellstart[NC + 1];
__device__ int    g_cellid[MAXF];
__device__ float4 g_scent[MAXF];       // cell-sorted centroids
__device__ int    g_sface[MAXF];       // original face index per sorted slot

// canonical squared distance bits: d = max(2*((ci_h + cj_h) - dot), 0)
__device__ __forceinline__ unsigned canon_bits(float4 c, float4 a) {
    float dot = c.x * a.x + c.y * a.y + c.z * a.z;
    float d = fmaxf(2.0f * ((c.w + a.w) - dot), 0.0f);
    return __float_as_uint(d);
}

__device__ __forceinline__ int bin1(float x) {
    int i = (int)floorf((x - BMIN) * INVH);
    return i < 0 ? 0 : (i > G - 1 ? G - 1 : i);
}

// ---------------- kernel 1: per-face geometry + cell binning ----------------
__global__ void prep_kernel(const float* __restrict__ verts,
                            const int* __restrict__ faces, int F) {
    int f = blockIdx.x * blockDim.x + threadIdx.x;
    if (f >= F) return;
    int i0 = faces[3 * f + 0], i1 = faces[3 * f + 1], i2 = faces[3 * f + 2];
    float v0x = verts[3 * i0 + 0], v0y = verts[3 * i0 + 1], v0z = verts[3 * i0 + 2];
    float v1x = verts[3 * i1 + 0], v1y = verts[3 * i1 + 1], v1z = verts[3 * i1 + 2];
    float v2x = verts[3 * i2 + 0], v2y = verts[3 * i2 + 1], v2z = verts[3 * i2 + 2];

    float e1x = v1x - v0x, e1y = v1y - v0y, e1z = v1z - v0z;
    float e2x = v2x - v0x, e2y = v2y - v0y, e2z = v2z - v0z;
    float nx = e1y * e2z - e1z * e2y;
    float ny = e1z * e2x - e1x * e2z;
    float nz = e1x * e2y - e1y * e2x;
    float nn = sqrtf(nx * nx + ny * ny + nz * nz) + 1e-8f;

    float cx = (v0x + v1x + v2x) / 3.0f;
    float cy = (v0y + v1y + v2y) / 3.0f;
    float cz = (v0z + v1z + v2z) / 3.0f;
    float hsq = 0.5f * (cx * cx + cy * cy + cz * cz);

    g_cent4[f] = make_float4(cx, cy, cz, hsq);
    g_v0[f]    = make_float4(v0x, v0y, v0z, 0.f);
    g_v1[f]    = make_float4(v1x, v1y, v1z, 0.f);
    g_v2[f]    = make_float4(v2x, v2y, v2z, 0.f);
    g_nun[f]   = make_float4(nx, ny, nz, 0.f);
    g_nrm[f]   = make_float4(nx / nn, ny / nn, nz / nn, 0.f);

    int c = (bin1(cz) * G + bin1(cy)) * G + bin1(cx);
    g_cellid[f] = c;
    atomicAdd(&g_cellcnt[c], 1);
}

// ---------------- single-block exclusive scan of g_cellcnt (NC=32768) ------
__global__ void scan_kernel() {
    __shared__ int s[1024];
    int t = threadIdx.x;
    int base = t * 32;
    int loc[32];
    int sum = 0;
    #pragma unroll
    for (int i = 0; i < 32; ++i) { loc[i] = g_cellcnt[base + i]; sum += loc[i]; }
    s[t] = sum;
    __syncthreads();
    for (int o = 1; o < 1024; o <<= 1) {
        int add = (t >= o) ? s[t - o] : 0;
        __syncthreads();
        s[t] += add;
        __syncthreads();
    }
    int pre = s[t] - sum;
    #pragma unroll
    for (int i = 0; i < 32; ++i) { g_cellstart[base + i] = pre; pre += loc[i]; }
    if (t == 1023) g_cellstart[NC] = pre;
}

// ---------------- scatter into cell-sorted order ----------------
__global__ void scatter_kernel(int F) {
    int f = blockIdx.x * blockDim.x + threadIdx.x;
    if (f >= F) return;
    int c = g_cellid[f];
    int pos = g_cellstart[c] + atomicAdd(&g_cellfill[c], 1);
    g_scent[pos] = g_cent4[f];
    g_sface[pos] = f;
}

// ------ query: exact grid kNN + fused collision count, one warp per row ----
__global__ void __launch_bounds__(128, 8) query_kernel(
        const int* __restrict__ faces, const float* __restrict__ prob,
        int F, int kp1) {
    __shared__ ull bufs[4 * CAP];
    __shared__ int hist[4 * NBIN];

    int tid = threadIdx.x;
    int lane = tid & 31;
    int w = tid >> 5;
    int ri = blockIdx.x * 4 + w;
    if (ri >= F) return;
    const unsigned FULL = 0xffffffffu;
    unsigned lmask = (1u << lane) - 1u;

    ull* bw = bufs + w * CAP;
    int* h = hist + w * NBIN;

    float4 qv = g_cent4[ri];
    int cx = bin1(qv.x), cy = bin1(qv.y), cz = bin1(qv.z);

    int cnt = 0;
    unsigned thr = 0x7F800000u;
    float thrpv = __int_as_float(0x7F800000);

    // warp-local compaction: tighten thr, filter buffer in place
    auto compact = [&]() {
        for (int b = lane; b < NBIN; b += 32) h[b] = 0;
        __syncwarp();
        for (int e = lane; e < cnt; e += 32)
            atomicAdd(&h[(unsigned)(bw[e] >> 54)], 1);
        __syncwarp();
        int b0l = lane * 16, s = 0;
        #pragma unroll
        for (int b = 0; b < 16; ++b) s += h[b0l + b];
        int cum = s;
        #pragma unroll
        for (int o = 1; o < 32; o <<= 1) {
            int t = __shfl_up_sync(FULL, cum, o);
            if (lane >= o) cum += t;
        }
        unsigned bal = __ballot_sync(FULL, cum >= kp1);
        int L = __ffs(bal) - 1;
        int cbef = __shfl_sync(FULL, cum - s, L);
        int Bc = 0, cB = 0;
        if (lane == L) {
            int c = cbef, b = L * 16;
            for (;; ++b) { if (c + h[b] >= kp1) break; c += h[b]; }
            Bc = b; cB = c;
        }
        Bc = __shfl_sync(FULL, Bc, L);
        cB = __shfl_sync(FULL, cB, L);
        __syncwarp();
        if (lane < 16) h[lane] = 0;
        __syncwarp();
        for (int e = lane; e < cnt; e += 32) {
            unsigned bits = (unsigned)(bw[e] >> 32);
            if ((bits >> 22) == (unsigned)Bc)
                atomicAdd(&h[(bits >> 18) & 15], 1);
        }
        __syncwarp();
        int S = 0;
        if (lane == 0) {
            int c = cB, ssb = 0;
            for (;; ++ssb) { if (c + h[ssb] >= kp1) break; c += h[ssb]; }
            S = ssb;
        }
        S = __shfl_sync(FULL, S, 0);
        unsigned fine = ((unsigned)Bc << 4) | (unsigned)S;
        unsigned thrb = (fine + 1u) << 18;
        if (thrb > 0x7F800000u) thrb = 0x7F800000u;
        unsigned thrp = (fine + 2u) << 18;
        if (thrp > 0x7F800000u) thrp = 0x7F800000u;
        int nb = 0;
        for (int i0 = 0; i0 < cnt; i0 += 32) {
            int e = i0 + lane;
            ull v = (e < cnt) ? bw[e] : ~0ull;
            bool keep = (e < cnt) && ((unsigned)(v >> 32) < thrb);
            unsigned m = __ballot_sync(FULL, keep);
            int pos = nb + __popc(m & lmask);
            __syncwarp();
            if (keep) bw[pos] = v;
            nb += __popc(m);
            __syncwarp();
        }
        cnt = nb;
        thr = thrb;
        thrpv = __uint_as_float(thrp);
    };

    // dense push of a contiguous sorted-point span [s0,s1)
    auto pushspan = [&](int s0, int s1) {
        for (int base = s0; base < s1; base += 32) {
            if (cnt + 32 > CAP && cnt >= kp1) compact();
            int e = base + lane;
            bool act = e < s1;
            unsigned db = 0; unsigned jf = 0;
            if (act) {
                float4 a = g_scent[e];
                jf = (unsigned)g_sface[e];
                db = canon_bits(qv, a);
                act = db < thr;
            }
            unsigned m = __ballot_sync(FULL, act);
            if (act) bw[cnt + __popc(m & lmask)] = ((ull)db << 32) | jf;
            cnt += __popc(m);
            if (cnt > CAP) cnt = CAP;
        }
    };

    // ---- find minimal box R with count >= kp1 (prefix-sum count only) ----
    int R = 0;
    int z0, z1, y0, y1, x0, x1;
    for (;;) {
        z0 = cz - R; if (z0 < 0) z0 = 0;
        z1 = cz + R; if (z1 > G - 1) z1 = G - 1;
        y0 = cy - R; if (y0 < 0) y0 = 0;
        y1 = cy + R; if (y1 > G - 1) y1 = G - 1;
        x0 = cx - R; if (x0 < 0) x0 = 0;
        x1 = cx + R; if (x1 > G - 1) x1 = G - 1;
        int ny = y1 - y0 + 1;
        int nrows = (z1 - z0 + 1) * ny;
        int total = 0;
        for (int b = lane; b < nrows; b += 32) {
            int az = z0 + b / ny, ay = y0 + b % ny;
            int rowb = (az * G + ay) * G;
            total += g_cellstart[rowb + x1 + 1] - g_cellstart[rowb + x0];
        }
        #pragma unroll
        for (int o = 16; o; o >>= 1) total += __shfl_xor_sync(FULL, total, o);
        if (total >= kp1 || R >= G) break;
        ++R;
    }

    // ---- phase A: push every row-span of box R (lane-parallel lookups) ----
    {
        int ny = y1 - y0 + 1;
        int nrows = (z1 - z0 + 1) * ny;
        for (int b0 = 0; b0 < nrows; b0 += 32) {
            int b = b0 + lane;
            int s0 = 0, s1 = 0;
            if (b < nrows) {
                int az = z0 + b / ny, ay = y0 + b % ny;
                int rowb = (az * G + ay) * G;
                s0 = g_cellstart[rowb + x0];
                s1 = g_cellstart[rowb + x1 + 1];
            }
            unsigned act = __ballot_sync(FULL, s1 > s0);
            while (act) {
                int L = __ffs(act) - 1; act &= act - 1;
                int t0 = __shfl_sync(FULL, s0, L);
                int t1 = __shfl_sync(FULL, s1, L);
                pushspan(t0, t1);
            }
        }
        compact();
    }

    // ---- phase B: all cells with box-mindist^2 < thr outside box R ----
    {
        float rt = sqrtf(thrpv) * 1.0001f + 1e-7f;
        int bz0 = bin1(qv.z - rt), bz1 = bin1(qv.z + rt);
        int by0 = bin1(qv.y - rt), by1 = bin1(qv.y + rt);
        int my = by1 - by0 + 1;
        int nr = (bz1 - bz0 + 1) * my;
        for (int b0 = 0; b0 < nr; b0 += 32) {
            int b = b0 + lane;
            int s0a = 0, s1a = 0, s0b = 0, s1b = 0;
            if (b < nr) {
                int az = bz0 + b / my, ay = by0 + b % my;
                float loz = BMIN + az * HH, hiz = loz + HH;
                float dzm = fmaxf(fmaxf((az == 0) ? 0.f : loz - qv.z,
                                        (az == G - 1) ? 0.f : qv.z - hiz), 0.f);
                float dz2 = dzm * dzm;
                if (dz2 < thrpv) {
                    float loy = BMIN + ay * HH, hiy = loy + HH;
                    float dym = fmaxf(fmaxf((ay == 0) ? 0.f : loy - qv.y,
                                            (ay == G - 1) ? 0.f : qv.y - hiy), 0.f);
                    float dzy = dz2 + dym * dym;
                    if (dzy < thrpv) {
                        float dxa = sqrtf(thrpv - dzy) * 1.0001f + 1e-7f;
                        int axlo = bin1(qv.x - dxa), axhi = bin1(qv.x + dxa);
                        int rowb = (az * G + ay) * G;
                        bool inbox = (az >= z0 && az <= z1 && ay >= y0 && ay <= y1);
                        if (inbox) {
                            if (axlo <= x0 - 1) {
                                s0a = g_cellstart[rowb + axlo];
                                s1a = g_cellstart[rowb + x0];
                            }
                            if (axhi >= x1 + 1) {
                                s0b = g_cellstart[rowb + x1 + 1];
                                s1b = g_cellstart[rowb + axhi + 1];
                            }
                        } else {
                            s0a = g_cellstart[rowb + axlo];
                            s1a = g_cellstart[rowb + axhi + 1];
                        }
                    }
                }
            }
            unsigned act = __ballot_sync(FULL, (s1a > s0a) | (s1b > s0b));
            while (act) {
                int L = __ffs(act) - 1; act &= act - 1;
                int t0 = __shfl_sync(FULL, s0a, L);
                int t1 = __shfl_sync(FULL, s1a, L);
                int u0 = __shfl_sync(FULL, s0b, L);
                int u1 = __shfl_sync(FULL, s1b, L);
                if (t1 > t0) pushspan(t0, t1);
                if (u1 > u0) pushspan(u0, u1);
            }
        }
    }

    compact();

    // ---- fused: rank-count + collision test + warp-reduced contribution ----
    int i = ri;
    int a0 = faces[3 * i + 0], a1 = faces[3 * i + 1], a2 = faces[3 * i + 2];
    bool fz1 = (a1 != a0);
    bool fz2 = (a2 != a0) && (a2 != a1);
    float4 v0i = g_v0[i], v1i = g_v1[i], v2i = g_v2[i];
    float4 ni  = g_nun[i], mi = g_nrm[i], ci = g_cent4[i];

    int colcnt = 0;
    for (int e = lane; e < cnt; e += 32) {
        ull ke = bw[e];
        int rank = 0;
        for (int qq = 0; qq < cnt; ++qq) rank += (bw[qq] < ke);
        // rank 0 = global min (self / lowest-index tie) -> dropped
        if (rank >= 1 && rank < kp1) {
            int j = (int)(ke & 0xffffffffu);
            float4 v0j = g_v0[j], v1j = g_v1[j], v2j = g_v2[j];
            float4 nj  = g_nun[j], mj = g_nrm[j], cj = g_cent4[j];

            float ndot = fabsf(mi.x * mj.x + mi.y * mj.y + mi.z * mj.z);
            bool coplanar = ndot > 0.99f;

            bool inter;
            if (coplanar) {
                float dx = ci.x - cj.x, dy = ci.y - cj.y, dz = ci.z - cj.z;
                inter = sqrtf(dx * dx + dy * dy + dz * dz) < 1e-10f;
            } else {
                float dA0 = (v0j.x - v0i.x) * ni.x + (v0j.y - v0i.y) * ni.y + (v0j.z - v0i.z) * ni.z;
                float dA1 = (v1j.x - v0i.x) * ni.x + (v1j.y - v0i.y) * ni.y + (v1j.z - v0i.z) * ni.z;
                float dA2 = (v2j.x - v0i.x) * ni.x + (v2j.y - v0i.y) * ni.y + (v2j.z - v0i.z) * ni.z;
                bool condA = (dA0 * dA1 <= 0.f) || (dA0 * dA2 <= 0.f) || (dA1 * dA2 <= 0.f);
                float dB0 = (v0i.x - v0j.x) * nj.x + (v0i.y - v0j.y) * nj.y + (v0i.z - v0j.z) * nj.z;
                float dB1 = (v1i.x - v0j.x) * nj.x + (v1i.y - v0j.y) * nj.y + (v1i.z - v0j.z) * nj.z;
                float dB2 = (v2i.x - v0j.x) * nj.x + (v2i.y - v0j.y) * nj.y + (v2i.z - v0j.z) * nj.z;
                bool condB = (dB0 * dB1 <= 0.f) || (dB0 * dB2 <= 0.f) || (dB1 * dB2 <= 0.f);
                inter = condA && condB;
            }

            int b0 = faces[3 * j + 0], b1 = faces[3 * j + 1], b2 = faces[3 * j + 2];
            int shared = 0;
            if (a0 == b0 || a0 == b1 || a0 == b2) shared++;
            if (fz1 && (a1 == b0 || a1 == b1 || a1 == b2)) shared++;
            if (fz2 && (a2 == b0 || a2 == b1 || a2 == b2)) shared++;
            bool adjacent = shared >= 2;

            colcnt += (inter && !adjacent) ? 1 : 0;
        }
    }
    #pragma unroll
    for (int o = 16; o; o >>= 1) colcnt += __shfl_xor_sync(FULL, colcnt, o);
    if (lane == 0) g_contrib[ri] = prob[ri] * (float)colcnt;
}

// ---------------- deterministic two-stage reduction ------------
__global__ void reduce1_kernel(int F) {
    __shared__ double ps[256];
    int tid = threadIdx.x;
    double s = 0.0;
    for (int i = blockIdx.x * 256 + tid; i < F; i += RB * 256)
        s += (double)g_contrib[i];
    ps[tid] = s;
    __syncthreads();
    for (int o = 128; o; o >>= 1) {
        if (tid < o) ps[tid] += ps[tid + o];
        __syncthreads();
    }
    if (tid == 0) g_partial[blockIdx.x] = ps[0];
}

__global__ void reduce2_kernel(float* __restrict__ out) {
    __shared__ double ps[RB];
    int tid = threadIdx.x;
    ps[tid] = g_partial[tid];
    __syncthreads();
    for (int o = RB / 2; o; o >>= 1) {
        if (tid < o) ps[tid] += ps[tid + o];
        __syncthreads();
    }
    if (tid == 0) out[0] = (float)ps[0];
}

// ---------------- cleanup: restore zeroed counters for next replay --------
__global__ void cleanup_kernel() {
    int i = blockIdx.x * blockDim.x + threadIdx.x;
    if (i < NC) { g_cellcnt[i] = 0; g_cellfill[i] = 0; }
}

// ---------------- launch ----------------
extern "C" void kernel_launch(void* const* d_in, const int* in_sizes, int n_in,
                              void* d_out, int out_size) {
    const float* verts = (const float*)d_in[0];
    const int*   faces = (const int*)d_in[1];
    const float* prob  = (const float*)d_in[2];
    float* out = (float*)d_out;

    int F = in_sizes[1] / 3;
    if (F > MAXF) F = MAXF;
    int kk = (F - 1 < KK) ? (F - 1) : KK;
    int kp1 = kk + 1;

    prep_kernel<<<(F + 255) / 256, 256>>>(verts, faces, F);
    scan_kernel<<<1, 1024>>>();
    scatter_kernel<<<(F + 255) / 256, 256>>>(F);

    query_kernel<<<(F + 3) / 4, 128>>>(faces, prob, F, kp1);  // 4th launch: profiled

    reduce1_kernel<<<RB, 256>>>(F);
    reduce2_kernel<<<1, RB>>>(out);

    cleanup_kernel<<<(NC + 255) / 256, 256>>>();
}